// round 14
// baseline (speedup 1.0000x reference)
#include <cuda_runtime.h>
#include <mma.h>
#include <cstdint>

using namespace nvcuda;

#define BATCH 64
#define SEQT  1024
#define IDIM  256
#define HDIM  512
#define G4    2048   // 4*H

// ---------------- scratch (device globals; no allocation allowed) ----------------
__device__ float g_xt [(size_t)BATCH * SEQT * IDIM]; // transposed input (B,T,I), tf32-rounded
__device__ float g_xp [(size_t)BATCH * SEQT * G4];   // precomputed input gates (B*T, 4H)
__device__ float g_ys0[(size_t)BATCH * SEQT * HDIM]; // layer-0 outputs, tf32-rounded
__device__ float g_wih[(size_t)G4 * HDIM];           // tf32-rounded W_ih scratch
__device__ float g_h  [2][BATCH * HDIM];             // h double buffer
__device__ unsigned g_cnt [4][SEQT];                 // full-group write-gate flags
__device__ unsigned g_qcnt[4][8][SEQT];              // per-quad producer flags (target 4)

__device__ __forceinline__ float tanh_fast(float x) {
    float y;
    asm("tanh.approx.f32 %0, %1;" : "=f"(y) : "f"(x));
    return y;
}
__device__ __forceinline__ float sigmoid_fast(float x) {
    return 0.5f + 0.5f * tanh_fast(0.5f * x);
}

// ---------------- transpose: x (B,I,T) -> xt (B,T,I), tf32-rounded ----------------
__global__ void transpose_kernel(const float* __restrict__ x) {
    __shared__ float tile[32][33];
    int b  = blockIdx.z;
    int t0 = blockIdx.x * 32;
    int i0 = blockIdx.y * 32;
    const float* xb = x + (size_t)b * IDIM * SEQT;
    #pragma unroll
    for (int k = 0; k < 32; k += 8) {
        int i = i0 + threadIdx.y + k;
        tile[threadIdx.y + k][threadIdx.x] =
            wmma::__float_to_tf32(xb[(size_t)i * SEQT + t0 + threadIdx.x]);
    }
    __syncthreads();
    float* xtb = g_xt + (size_t)b * SEQT * IDIM;
    #pragma unroll
    for (int k = 0; k < 32; k += 8) {
        int t = t0 + threadIdx.y + k;
        xtb[(size_t)t * IDIM + i0 + threadIdx.x] = tile[threadIdx.x][threadIdx.y + k];
    }
}

// ---------------- round W_ih to tf32 grid ----------------
__global__ void prep_w_kernel(const float* __restrict__ W, int n) {
    int i = blockIdx.x * blockDim.x + threadIdx.x;
    for (int k = i; k < n; k += gridDim.x * blockDim.x)
        g_wih[k] = wmma::__float_to_tf32(W[k]);
}

// ---------------- zero h buffers + barrier counters ----------------
__global__ void zero_kernel() {
    int i = blockIdx.x * blockDim.x + threadIdx.x;
    int n = 2 * BATCH * HDIM;
    float* h = &g_h[0][0];
    for (int k = i; k < n; k += gridDim.x * blockDim.x) h[k] = 0.0f;
    unsigned* c = &g_cnt[0][0];
    for (int k = i; k < 4 * SEQT; k += gridDim.x * blockDim.x) c[k] = 0u;
    unsigned* q = &g_qcnt[0][0][0];
    for (int k = i; k < 4 * 8 * SEQT; k += gridDim.x * blockDim.x) q[k] = 0u;
}

// ---------------- TF32 GEMM (cp.async 3-stage):  C[m,n] = sum_k A[m,k]*W[n,k] --
// Inputs MUST be pre-rounded to the tf32 grid (HW truncation is then exact).
#define GBM 128
#define GBN 128
#define GBK 32
#define SLD 36        // 32 + 4 pad; 36*4 = 144 B -> cp.async dst stays 16B-aligned
#define NSTAGE 3

__global__ void __launch_bounds__(256, 2) gemm_tf32_kernel(
    const float* __restrict__ A, const float* __restrict__ W,
    float* __restrict__ C, int K)
{
    extern __shared__ float gs[];   // NSTAGE x (sA 128xSLD + sB 128xSLD)
    int tid = threadIdx.x;
    int m0  = blockIdx.y * GBM;
    int n0  = blockIdx.x * GBN;
    int warp = tid >> 5;
    int wm = warp >> 2;   // 0..1 : 64 rows each
    int wn = warp & 3;    // 0..3 : 32 cols each

    wmma::fragment<wmma::accumulator, 16, 16, 8, float> cf[4][2];
    #pragma unroll
    for (int i = 0; i < 4; ++i)
        #pragma unroll
        for (int j = 0; j < 2; ++j)
            wmma::fill_fragment(cf[i][j], 0.0f);

    uint32_t sbase;
    asm("{ .reg .u64 t; cvta.to.shared.u64 t, %1; cvt.u32.u64 %0, t; }"
        : "=r"(sbase) : "l"(gs));

    int nk = K / GBK;

    auto issue = [&](int kt) {
        int buf = kt % NSTAGE;
        int k0  = kt * GBK;
        uint32_t sA = sbase + (uint32_t)buf * (2u * GBM * SLD * 4u);
        uint32_t sB = sA + GBM * SLD * 4u;
        #pragma unroll
        for (int i = 0; i < 4; ++i) {
            int fid = tid + i * 256;
            int r = fid >> 3, c4 = (fid & 7) << 2;
            asm volatile("cp.async.cg.shared.global [%0], [%1], 16;"
                :: "r"(sA + (uint32_t)(r * SLD + c4) * 4u),
                   "l"(&A[(size_t)(m0 + r) * K + k0 + c4]));
            asm volatile("cp.async.cg.shared.global [%0], [%1], 16;"
                :: "r"(sB + (uint32_t)(r * SLD + c4) * 4u),
                   "l"(&W[(size_t)(n0 + r) * K + k0 + c4]));
        }
    };

    issue(0); asm volatile("cp.async.commit_group;");
    issue(1); asm volatile("cp.async.commit_group;");
    asm volatile("cp.async.wait_group 1;");
    __syncthreads();

    for (int kt = 0; kt < nk; ++kt) {
        if (kt + 2 < nk) issue(kt + 2);
        asm volatile("cp.async.commit_group;");

        float* sA = gs + (kt % NSTAGE) * 2 * GBM * SLD;
        float* sB = sA + GBM * SLD;
        #pragma unroll
        for (int ks = 0; ks < GBK; ks += 8) {
            wmma::fragment<wmma::matrix_a, 16, 16, 8, wmma::precision::tf32, wmma::row_major> af[4];
            wmma::fragment<wmma::matrix_b, 16, 16, 8, wmma::precision::tf32, wmma::col_major> bf[2];
            #pragma unroll
            for (int i = 0; i < 4; ++i)
                wmma::load_matrix_sync(af[i], &sA[(wm * 64 + i * 16) * SLD + ks], SLD);
            #pragma unroll
            for (int j = 0; j < 2; ++j)
                wmma::load_matrix_sync(bf[j], &sB[(wn * 32 + j * 16) * SLD + ks], SLD);
            #pragma unroll
            for (int i = 0; i < 4; ++i)
                #pragma unroll
                for (int j = 0; j < 2; ++j)
                    wmma::mma_sync(cf[i][j], af[i], bf[j], cf[i][j]);
        }
        asm volatile("cp.async.wait_group 1;");
        __syncthreads();
    }
    #pragma unroll
    for (int i = 0; i < 4; ++i)
        #pragma unroll
        for (int j = 0; j < 2; ++j)
            wmma::store_matrix_sync(
                &C[(size_t)(m0 + wm * 64 + i * 16) * G4 + n0 + wn * 32 + j * 16],
                cf[i][j], G4, wmma::mem_row_major);
}

// ---------------- persistent LSTM scan (one layer) ----------------
// 128 CTAs x 512 threads. CTA: batch rows rb0..+15, hidden cols j0..+15.
// 16 warps = (nh 0..1) x (kq 0..7), weight fragments register-resident.
// Sync: quad flags (4 producers) gate staging+MMA; full-group flag gates the
// hdst write (write-after-read safety); ys stores after release.
#define SCAN_NB      128
#define SCAN_THREADS 512
#define SCAN_GRP     32     // CTAs per barrier group
#define WLD 520             // sH leading dim (mult of 4)
#define PLD 68              // partial tile leading dim (mult of 4)
#define TLD 68              // weight-init staging leading dim

__global__ void __launch_bounds__(SCAN_THREADS, 1) scan_kernel(
    const float* __restrict__ W_hh, const float* __restrict__ b_ih,
    const float* __restrict__ b_hh, float* __restrict__ ys,
    float* __restrict__ hid_out, float* __restrict__ cell_out,
    int round_ys)
{
    extern __shared__ float sm[];
    float* sH    = sm;                    // 16 x 520
    float* sPart = sH + 16 * WLD;         // 8 x 16 x PLD (reused as weight-init staging)

    int tid  = threadIdx.x;
    int lane = tid & 31;
    int cta  = blockIdx.x;
    int grp  = cta >> 5;          // batch group 0..3
    int rb0  = grp * 16;          // batch-tile origin
    int j0   = (cta & 31) * 16;   // hidden-tile origin
    int myq  = (cta & 31) >> 2;   // which quad this CTA's h columns belong to
    int warp = tid >> 5;          // 16 warps
    int nh   = warp & 1;          // N half: gate cols [nh*32, +32)
    int kq   = warp >> 1;         // K eighth: k in [kq*64, +64)

    // ---- load register-resident weight fragments (16 per warp) ----
    wmma::fragment<wmma::matrix_b, 16, 16, 8, wmma::precision::tf32, wmma::col_major> bfr[8][2];
    {
        float* sTmp = sPart;   // 64 x TLD staging, reused
        for (int q = 0; q < 8; ++q) {
            for (int idx = tid; idx < 64 * 64; idx += SCAN_THREADS) {
                int n = idx >> 6, kk = idx & 63;
                int g = (n >> 4) * HDIM + j0 + (n & 15);
                sTmp[n * TLD + kk] =
                    wmma::__float_to_tf32(W_hh[(size_t)g * HDIM + q * 64 + kk]);
            }
            __syncthreads();
            if (q == kq) {
                #pragma unroll
                for (int s = 0; s < 8; ++s)
                    #pragma unroll
                    for (int j = 0; j < 2; ++j)
                        wmma::load_matrix_sync(bfr[s][j],
                            &sTmp[(nh * 32 + j * 16) * TLD + s * 8], TLD);
            }
            __syncthreads();
        }
    }

    // ---- per-cell state for the 256 active elementwise threads ----
    int b_  = tid >> 4;        // 0..15 for tid<256
    int jj_ = tid & 15;
    float bias[4];
    if (tid < 256) {
        #pragma unroll
        for (int q = 0; q < 4; ++q) {
            int g = q * HDIM + j0 + jj_;
            bias[q] = b_ih[g] + b_hh[g];
        }
    }
    float creg = 0.0f;

    // prefetch xp for t = 0
    float rxp[4];
    if (tid < 256) {
        #pragma unroll
        for (int q = 0; q < 4; ++q)
            rxp[q] = g_xp[((size_t)(rb0 + b_) * SEQT + 0) * G4 + q * HDIM + j0 + jj_];
    }

    for (int t = 0; t < SEQT; ++t) {
        // fine-grained: wait only for this warp's 4 producer CTAs (quad kq)
        if (t > 0) {
            const unsigned* qptr = &g_qcnt[grp][kq][t - 1];
            unsigned v;
            do {
                asm volatile("ld.acquire.gpu.global.u32 %0, [%1];"
                             : "=r"(v) : "l"(qptr) : "memory");
            } while (v < 4u);
        }

        const float* hsrc = g_h[t & 1];
        float*       hdst = g_h[(t + 1) & 1];

        // stage OWN K-slice of h: warp (kq, nh) stages rows nh*8..+8, cols kq*64..+64
        {
            const float* src = &hsrc[rb0 * HDIM + kq * 64];
            #pragma unroll
            for (int e = 0; e < 4; ++e) {
                int idx = e * 32 + lane;        // 0..127
                int r   = nh * 8 + (idx >> 4);  // row in tile
                int c4  = (idx & 15) << 2;      // col within slice
                float4 v = __ldcv((const float4*)&src[r * HDIM + c4]);
                float* d = &sH[r * WLD + kq * 64 + c4];
                d[0] = wmma::__float_to_tf32(v.x);
                d[1] = wmma::__float_to_tf32(v.y);
                d[2] = wmma::__float_to_tf32(v.z);
                d[3] = wmma::__float_to_tf32(v.w);
            }
        }
        // sync only with pair partner (other nh of same kq): named barrier, 64 threads
        asm volatile("bar.sync %0, %1;" :: "r"(kq + 1), "r"(64) : "memory");

        // partial gates: acc[j] = sum over this warp's K64 of h @ W^T
        {
            wmma::fragment<wmma::accumulator, 16, 16, 8, float> acc[2];
            wmma::fill_fragment(acc[0], 0.0f);
            wmma::fill_fragment(acc[1], 0.0f);
            #pragma unroll
            for (int s = 0; s < 8; ++s) {
                wmma::fragment<wmma::matrix_a, 16, 16, 8, wmma::precision::tf32, wmma::row_major> af;
                wmma::load_matrix_sync(af, &sH[kq * 64 + s * 8], WLD);
                wmma::mma_sync(acc[0], af, bfr[s][0], acc[0]);
                wmma::mma_sync(acc[1], af, bfr[s][1], acc[1]);
            }
            float* dst = &sPart[kq * 16 * PLD + nh * 32];
            wmma::store_matrix_sync(dst,      acc[0], PLD, wmma::mem_row_major);
            wmma::store_matrix_sync(dst + 16, acc[1], PLD, wmma::mem_row_major);
        }

        // full-group write-gate: non-EW warps poll; syncthreads publishes to all
        if (t > 0 && tid >= 256) {
            const unsigned* cptr = &g_cnt[grp][t - 1];
            unsigned v;
            do {
                asm volatile("ld.acquire.gpu.global.u32 %0, [%1];"
                             : "=r"(v) : "l"(cptr) : "memory");
            } while (v < (unsigned)SCAN_GRP);
        }
        __syncthreads();

        // fused K-reduce + elementwise; store ONLY hdst here (critical path)
        float hval = 0.0f, cval = 0.0f;
        if (tid < 256) {
            float gs_[4];
            #pragma unroll
            for (int q = 0; q < 4; ++q) {
                float g = rxp[q] + bias[q];
                int col = q * 16 + jj_;
                #pragma unroll
                for (int p = 0; p < 8; ++p)
                    g += sPart[p * 16 * PLD + b_ * PLD + col];
                gs_[q] = g;
            }
            float si = sigmoid_fast(gs_[0]);
            float sf = sigmoid_fast(gs_[1]);
            float tg = tanh_fast(gs_[2]);
            float so = sigmoid_fast(gs_[3]);
            cval = sf * creg + si * tg;
            creg = cval;
            hval = so * tanh_fast(cval);
            hdst[(rb0 + b_) * HDIM + j0 + jj_] = hval;
        }
        __syncthreads();   // h stores complete before arrival

        if (t != SEQT - 1) {
            if (tid == 0) {
                asm volatile("red.release.gpu.global.add.u32 [%0], %1;"
                             :: "l"(&g_cnt[grp][t]), "r"(1u) : "memory");
                asm volatile("red.release.gpu.global.add.u32 [%0], %1;"
                             :: "l"(&g_qcnt[grp][myq][t]), "r"(1u) : "memory");
            }
        }

        // off-critical-path stores + next-step xp prefetch
        if (tid < 256) {
            int bg = rb0 + b_, jg = j0 + jj_;
            float hy = round_ys ? wmma::__float_to_tf32(hval) : hval;
            ys[((size_t)bg * SEQT + t) * HDIM + jg] = hy;
            if (t == SEQT - 1) {
                hid_out [bg * HDIM + jg] = hval;
                cell_out[bg * HDIM + jg] = cval;
            } else {
                #pragma unroll
                for (int q = 0; q < 4; ++q)
                    rxp[q] = g_xp[((size_t)bg * SEQT + (t + 1)) * G4
                                  + q * HDIM + j0 + jj_];
            }
        }
    }
}

// ---------------- launch ----------------
extern "C" void kernel_launch(void* const* d_in, const int* in_sizes, int n_in,
                              void* d_out, int out_size)
{
    const float* x     = (const float*)d_in[0];
    const float* W_ih0 = (const float*)d_in[1];
    const float* W_hh0 = (const float*)d_in[2];
    const float* b_ih0 = (const float*)d_in[3];
    const float* b_hh0 = (const float*)d_in[4];
    const float* W_ih1 = (const float*)d_in[5];
    const float* W_hh1 = (const float*)d_in[6];
    const float* b_ih1 = (const float*)d_in[7];
    const float* b_hh1 = (const float*)d_in[8];
    float* out = (float*)d_out;

    float *p_xt = nullptr, *p_ys0 = nullptr, *p_xp = nullptr, *p_w = nullptr;
    cudaGetSymbolAddress((void**)&p_xt,  g_xt);
    cudaGetSymbolAddress((void**)&p_ys0, g_ys0);
    cudaGetSymbolAddress((void**)&p_xp,  g_xp);
    cudaGetSymbolAddress((void**)&p_w,   g_wih);

    const size_t OUT_BTH = (size_t)BATCH * SEQT * HDIM;   // 33,554,432
    float* hid0  = out + OUT_BTH;
    float* hid1  = hid0 + BATCH * HDIM;
    float* cell0 = out + OUT_BTH + 2 * BATCH * HDIM;
    float* cell1 = cell0 + BATCH * HDIM;

    const int scan_smem = (16 * WLD + 8 * 16 * PLD) * sizeof(float);
    cudaFuncSetAttribute(scan_kernel, cudaFuncAttributeMaxDynamicSharedMemorySize, scan_smem);
    const int gemm_smem = NSTAGE * 2 * GBM * SLD * sizeof(float);   // 110592
    cudaFuncSetAttribute(gemm_tf32_kernel, cudaFuncAttributeMaxDynamicSharedMemorySize, gemm_smem);

    // 1) transpose x -> (B,T,I), tf32-rounded
    transpose_kernel<<<dim3(SEQT / 32, IDIM / 32, BATCH), dim3(32, 8)>>>(x);

    // 2) xp0 = xt @ W_ih0^T
    prep_w_kernel<<<256, 256>>>(W_ih0, G4 * IDIM);
    gemm_tf32_kernel<<<dim3(G4 / GBN, (BATCH * SEQT) / GBM), 256, gemm_smem>>>(p_xt, p_w, p_xp, IDIM);

    // 3) layer-0 scan (ys0 stored tf32-rounded for GEMM2)
    zero_kernel<<<256, 256>>>();
    scan_kernel<<<SCAN_NB, SCAN_THREADS, scan_smem>>>(W_hh0, b_ih0, b_hh0, p_ys0, hid0, cell0, 1);

    // 4) xp1 = ys0 @ W_ih1^T
    prep_w_kernel<<<256, 256>>>(W_ih1, G4 * HDIM);
    gemm_tf32_kernel<<<dim3(G4 / GBN, (BATCH * SEQT) / GBM), 256, gemm_smem>>>(p_ys0, p_w, p_xp, HDIM);

    // 5) layer-1 scan (writes directly into d_out)
    zero_kernel<<<256, 256>>>();
    scan_kernel<<<SCAN_NB, SCAN_THREADS, scan_smem>>>(W_hh1, b_ih1, b_hh1, out, hid1, cell1, 0);
}

// round 15
// speedup vs baseline: 1.0803x; 1.0803x over previous
#include <cuda_runtime.h>
#include <mma.h>
#include <cstdint>

using namespace nvcuda;

#define BATCH 64
#define SEQT  1024
#define IDIM  256
#define HDIM  512
#define G4    2048   // 4*H

// ---------------- scratch (device globals; no allocation allowed) ----------------
__device__ float g_xt [(size_t)BATCH * SEQT * IDIM]; // transposed input (B,T,I), tf32-rounded
__device__ float g_xp [(size_t)BATCH * SEQT * G4];   // precomputed input gates (B*T, 4H)
__device__ float g_ys0[(size_t)BATCH * SEQT * HDIM]; // layer-0 outputs, tf32-rounded
__device__ float g_wih[(size_t)G4 * HDIM];           // tf32-rounded W_ih scratch
__device__ float g_h  [2][BATCH * HDIM];             // h double buffer
__device__ unsigned g_cnt[4][SEQT][32];              // flags: one 128B line per (grp,t)

__device__ __forceinline__ float tanh_fast(float x) {
    float y;
    asm("tanh.approx.f32 %0, %1;" : "=f"(y) : "f"(x));
    return y;
}
__device__ __forceinline__ float sigmoid_fast(float x) {
    return 0.5f + 0.5f * tanh_fast(0.5f * x);
}

// ---------------- transpose: x (B,I,T) -> xt (B,T,I), tf32-rounded ----------------
__global__ void transpose_kernel(const float* __restrict__ x) {
    __shared__ float tile[32][33];
    int b  = blockIdx.z;
    int t0 = blockIdx.x * 32;
    int i0 = blockIdx.y * 32;
    const float* xb = x + (size_t)b * IDIM * SEQT;
    #pragma unroll
    for (int k = 0; k < 32; k += 8) {
        int i = i0 + threadIdx.y + k;
        tile[threadIdx.y + k][threadIdx.x] =
            wmma::__float_to_tf32(xb[(size_t)i * SEQT + t0 + threadIdx.x]);
    }
    __syncthreads();
    float* xtb = g_xt + (size_t)b * SEQT * IDIM;
    #pragma unroll
    for (int k = 0; k < 32; k += 8) {
        int t = t0 + threadIdx.y + k;
        xtb[(size_t)t * IDIM + i0 + threadIdx.x] = tile[threadIdx.x][threadIdx.y + k];
    }
}

// ---------------- round W_ih to tf32 grid ----------------
__global__ void prep_w_kernel(const float* __restrict__ W, int n) {
    int i = blockIdx.x * blockDim.x + threadIdx.x;
    for (int k = i; k < n; k += gridDim.x * blockDim.x)
        g_wih[k] = wmma::__float_to_tf32(W[k]);
}

// ---------------- zero h buffers + barrier counters ----------------
__global__ void zero_kernel() {
    int i = blockIdx.x * blockDim.x + threadIdx.x;
    int n = 2 * BATCH * HDIM;
    float* h = &g_h[0][0];
    for (int k = i; k < n; k += gridDim.x * blockDim.x) h[k] = 0.0f;
    unsigned* c = &g_cnt[0][0][0];
    for (int k = i; k < 4 * SEQT * 32; k += gridDim.x * blockDim.x) c[k] = 0u;
}

// ---------------- TF32 GEMM (cp.async 3-stage):  C[m,n] = sum_k A[m,k]*W[n,k] --
// Inputs MUST be pre-rounded to the tf32 grid (HW truncation is then exact).
#define GBM 128
#define GBN 128
#define GBK 32
#define SLD 36        // 32 + 4 pad; 36*4 = 144 B -> cp.async dst stays 16B-aligned
#define NSTAGE 3

__global__ void __launch_bounds__(256, 2) gemm_tf32_kernel(
    const float* __restrict__ A, const float* __restrict__ W,
    float* __restrict__ C, int K)
{
    extern __shared__ float gs[];   // NSTAGE x (sA 128xSLD + sB 128xSLD)
    int tid = threadIdx.x;
    int m0  = blockIdx.y * GBM;
    int n0  = blockIdx.x * GBN;
    int warp = tid >> 5;
    int wm = warp >> 2;   // 0..1 : 64 rows each
    int wn = warp & 3;    // 0..3 : 32 cols each

    wmma::fragment<wmma::accumulator, 16, 16, 8, float> cf[4][2];
    #pragma unroll
    for (int i = 0; i < 4; ++i)
        #pragma unroll
        for (int j = 0; j < 2; ++j)
            wmma::fill_fragment(cf[i][j], 0.0f);

    uint32_t sbase;
    asm("{ .reg .u64 t; cvta.to.shared.u64 t, %1; cvt.u32.u64 %0, t; }"
        : "=r"(sbase) : "l"(gs));

    int nk = K / GBK;

    auto issue = [&](int kt) {
        int buf = kt % NSTAGE;
        int k0  = kt * GBK;
        uint32_t sA = sbase + (uint32_t)buf * (2u * GBM * SLD * 4u);
        uint32_t sB = sA + GBM * SLD * 4u;
        #pragma unroll
        for (int i = 0; i < 4; ++i) {
            int fid = tid + i * 256;
            int r = fid >> 3, c4 = (fid & 7) << 2;
            asm volatile("cp.async.cg.shared.global [%0], [%1], 16;"
                :: "r"(sA + (uint32_t)(r * SLD + c4) * 4u),
                   "l"(&A[(size_t)(m0 + r) * K + k0 + c4]));
            asm volatile("cp.async.cg.shared.global [%0], [%1], 16;"
                :: "r"(sB + (uint32_t)(r * SLD + c4) * 4u),
                   "l"(&W[(size_t)(n0 + r) * K + k0 + c4]));
        }
    };

    issue(0); asm volatile("cp.async.commit_group;");
    issue(1); asm volatile("cp.async.commit_group;");
    asm volatile("cp.async.wait_group 1;");
    __syncthreads();

    for (int kt = 0; kt < nk; ++kt) {
        if (kt + 2 < nk) issue(kt + 2);
        asm volatile("cp.async.commit_group;");

        float* sA = gs + (kt % NSTAGE) * 2 * GBM * SLD;
        float* sB = sA + GBM * SLD;
        #pragma unroll
        for (int ks = 0; ks < GBK; ks += 8) {
            wmma::fragment<wmma::matrix_a, 16, 16, 8, wmma::precision::tf32, wmma::row_major> af[4];
            wmma::fragment<wmma::matrix_b, 16, 16, 8, wmma::precision::tf32, wmma::col_major> bf[2];
            #pragma unroll
            for (int i = 0; i < 4; ++i)
                wmma::load_matrix_sync(af[i], &sA[(wm * 64 + i * 16) * SLD + ks], SLD);
            #pragma unroll
            for (int j = 0; j < 2; ++j)
                wmma::load_matrix_sync(bf[j], &sB[(wn * 32 + j * 16) * SLD + ks], SLD);
            #pragma unroll
            for (int i = 0; i < 4; ++i)
                #pragma unroll
                for (int j = 0; j < 2; ++j)
                    wmma::mma_sync(cf[i][j], af[i], bf[j], cf[i][j]);
        }
        asm volatile("cp.async.wait_group 1;");
        __syncthreads();
    }
    #pragma unroll
    for (int i = 0; i < 4; ++i)
        #pragma unroll
        for (int j = 0; j < 2; ++j)
            wmma::store_matrix_sync(
                &C[(size_t)(m0 + wm * 64 + i * 16) * G4 + n0 + wn * 32 + j * 16],
                cf[i][j], G4, wmma::mem_row_major);
}

// ---------------- persistent LSTM scan (one layer) ----------------
// 128 CTAs x 512 threads. CTA: batch rows rb0..+15, hidden cols j0..+15.
// 16 warps = (nh 0..1) x (kq 0..7), weight fragments register-resident.
// Step: all-lane poll flag[t-1] -> per-pair stage sH (bar kq) -> MMA -> sPart
// -> syncthreads -> EW (tid<256) computes + stores h -> bar9(256) -> tid0
// releases flag[t]. Warps 8-15 skip EW/bar9 and pre-position at next poll.
#define SCAN_NB      128
#define SCAN_THREADS 512
#define SCAN_GRP     32     // CTAs per barrier group
#define WLD 520             // sH leading dim (mult of 4)
#define PLD 68              // partial tile leading dim (mult of 4)
#define TLD 68              // weight-init staging leading dim

__global__ void __launch_bounds__(SCAN_THREADS, 1) scan_kernel(
    const float* __restrict__ W_hh, const float* __restrict__ b_ih,
    const float* __restrict__ b_hh, float* __restrict__ ys,
    float* __restrict__ hid_out, float* __restrict__ cell_out,
    int round_ys)
{
    extern __shared__ float sm[];
    float* sH    = sm;                    // 16 x 520
    float* sPart = sH + 16 * WLD;         // 8 x 16 x PLD (reused as weight-init staging)

    int tid  = threadIdx.x;
    int lane = tid & 31;
    int cta  = blockIdx.x;
    int grp  = cta >> 5;          // batch group 0..3
    int rb0  = grp * 16;          // batch-tile origin
    int j0   = (cta & 31) * 16;   // hidden-tile origin
    int warp = tid >> 5;          // 16 warps
    int nh   = warp & 1;          // N half: gate cols [nh*32, +32)
    int kq   = warp >> 1;         // K eighth: k in [kq*64, +64)

    // ---- load register-resident weight fragments (16 per warp) ----
    wmma::fragment<wmma::matrix_b, 16, 16, 8, wmma::precision::tf32, wmma::col_major> bfr[8][2];
    {
        float* sTmp = sPart;   // 64 x TLD staging, reused
        for (int q = 0; q < 8; ++q) {
            for (int idx = tid; idx < 64 * 64; idx += SCAN_THREADS) {
                int n = idx >> 6, kk = idx & 63;
                int g = (n >> 4) * HDIM + j0 + (n & 15);
                sTmp[n * TLD + kk] =
                    wmma::__float_to_tf32(W_hh[(size_t)g * HDIM + q * 64 + kk]);
            }
            __syncthreads();
            if (q == kq) {
                #pragma unroll
                for (int s = 0; s < 8; ++s)
                    #pragma unroll
                    for (int j = 0; j < 2; ++j)
                        wmma::load_matrix_sync(bfr[s][j],
                            &sTmp[(nh * 32 + j * 16) * TLD + s * 8], TLD);
            }
            __syncthreads();
        }
    }

    // ---- per-cell state for the 256 active elementwise threads ----
    int b_  = tid >> 4;        // 0..15 for tid<256
    int jj_ = tid & 15;
    float bias[4];
    if (tid < 256) {
        #pragma unroll
        for (int q = 0; q < 4; ++q) {
            int g = q * HDIM + j0 + jj_;
            bias[q] = b_ih[g] + b_hh[g];
        }
    }
    float creg = 0.0f;

    // prefetch xp for t = 0
    float rxp[4];
    if (tid < 256) {
        #pragma unroll
        for (int q = 0; q < 4; ++q)
            rxp[q] = g_xp[((size_t)(rb0 + b_) * SEQT + 0) * G4 + q * HDIM + j0 + jj_];
    }

    for (int t = 0; t < SEQT; ++t) {
        // wait for previous step's h from all group peers (all-lane acquire poll)
        if (t > 0) {
            const unsigned* cptr = &g_cnt[grp][t - 1][0];
            unsigned v;
            do {
                asm volatile("ld.acquire.gpu.global.u32 %0, [%1];"
                             : "=r"(v) : "l"(cptr) : "memory");
            } while (v < (unsigned)SCAN_GRP);
        }

        const float* hsrc = g_h[t & 1];
        float*       hdst = g_h[(t + 1) & 1];

        // stage OWN K-slice of h: warp (kq, nh) stages rows nh*8..+8, cols kq*64..+64
        {
            const float* src = &hsrc[rb0 * HDIM + kq * 64];
            #pragma unroll
            for (int e = 0; e < 4; ++e) {
                int idx = e * 32 + lane;        // 0..127
                int r   = nh * 8 + (idx >> 4);  // row in tile
                int c4  = (idx & 15) << 2;      // col within slice
                float4 v = __ldcv((const float4*)&src[r * HDIM + c4]);
                float* d = &sH[r * WLD + kq * 64 + c4];
                d[0] = wmma::__float_to_tf32(v.x);
                d[1] = wmma::__float_to_tf32(v.y);
                d[2] = wmma::__float_to_tf32(v.z);
                d[3] = wmma::__float_to_tf32(v.w);
            }
        }
        // sync only with pair partner (other nh of same kq): named barrier, 64 threads
        asm volatile("bar.sync %0, %1;" :: "r"(kq + 1), "r"(64) : "memory");

        // partial gates: acc[j] = sum over this warp's K64 of h @ W^T
        {
            wmma::fragment<wmma::accumulator, 16, 16, 8, float> acc[2];
            wmma::fill_fragment(acc[0], 0.0f);
            wmma::fill_fragment(acc[1], 0.0f);
            #pragma unroll
            for (int s = 0; s < 8; ++s) {
                wmma::fragment<wmma::matrix_a, 16, 16, 8, wmma::precision::tf32, wmma::row_major> af;
                wmma::load_matrix_sync(af, &sH[kq * 64 + s * 8], WLD);
                wmma::mma_sync(acc[0], af, bfr[s][0], acc[0]);
                wmma::mma_sync(acc[1], af, bfr[s][1], acc[1]);
            }
            float* dst = &sPart[kq * 16 * PLD + nh * 32];
            wmma::store_matrix_sync(dst,      acc[0], PLD, wmma::mem_row_major);
            wmma::store_matrix_sync(dst + 16, acc[1], PLD, wmma::mem_row_major);
        }
        __syncthreads();   // publish sPart to EW threads

        // EW warps (0-7) finish the step; warps 8-15 jump to next-step poll
        // (their next sPart write is gated by flag[t] which tid0 releases only
        //  after all EW sPart reads are consumed -> no WAR hazard).
        if (tid < 256) {
            float gs_[4];
            #pragma unroll
            for (int q = 0; q < 4; ++q) {
                float g = rxp[q] + bias[q];
                int col = q * 16 + jj_;
                #pragma unroll
                for (int p = 0; p < 8; ++p)
                    g += sPart[p * 16 * PLD + b_ * PLD + col];
                gs_[q] = g;
            }
            float si = sigmoid_fast(gs_[0]);
            float sf = sigmoid_fast(gs_[1]);
            float tg = tanh_fast(gs_[2]);
            float so = sigmoid_fast(gs_[3]);
            float cval = sf * creg + si * tg;
            creg = cval;
            float hval = so * tanh_fast(cval);
            int bg = rb0 + b_, jg = j0 + jj_;
            hdst[bg * HDIM + jg] = hval;

            // 256-thread named barrier: all EW h-stores issued & values consumed
            asm volatile("bar.sync 9, 256;" ::: "memory");
            if (t != SEQT - 1 && tid == 0) {
                asm volatile("red.release.gpu.global.add.u32 [%0], %1;"
                             :: "l"(&g_cnt[grp][t][0]), "r"(1u) : "memory");
            }

            // off-critical-path stores + next-step xp prefetch
            float hy = round_ys ? wmma::__float_to_tf32(hval) : hval;
            ys[((size_t)bg * SEQT + t) * HDIM + jg] = hy;
            if (t == SEQT - 1) {
                hid_out [bg * HDIM + jg] = hval;
                cell_out[bg * HDIM + jg] = cval;
            } else {
                #pragma unroll
                for (int q = 0; q < 4; ++q)
                    rxp[q] = g_xp[((size_t)bg * SEQT + (t + 1)) * G4
                                  + q * HDIM + j0 + jj_];
            }
        }
    }
}

// ---------------- launch ----------------
extern "C" void kernel_launch(void* const* d_in, const int* in_sizes, int n_in,
                              void* d_out, int out_size)
{
    const float* x     = (const float*)d_in[0];
    const float* W_ih0 = (const float*)d_in[1];
    const float* W_hh0 = (const float*)d_in[2];
    const float* b_ih0 = (const float*)d_in[3];
    const float* b_hh0 = (const float*)d_in[4];
    const float* W_ih1 = (const float*)d_in[5];
    const float* W_hh1 = (const float*)d_in[6];
    const float* b_ih1 = (const float*)d_in[7];
    const float* b_hh1 = (const float*)d_in[8];
    float* out = (float*)d_out;

    float *p_xt = nullptr, *p_ys0 = nullptr, *p_xp = nullptr, *p_w = nullptr;
    cudaGetSymbolAddress((void**)&p_xt,  g_xt);
    cudaGetSymbolAddress((void**)&p_ys0, g_ys0);
    cudaGetSymbolAddress((void**)&p_xp,  g_xp);
    cudaGetSymbolAddress((void**)&p_w,   g_wih);

    const size_t OUT_BTH = (size_t)BATCH * SEQT * HDIM;   // 33,554,432
    float* hid0  = out + OUT_BTH;
    float* hid1  = hid0 + BATCH * HDIM;
    float* cell0 = out + OUT_BTH + 2 * BATCH * HDIM;
    float* cell1 = cell0 + BATCH * HDIM;

    const int scan_smem = (16 * WLD + 8 * 16 * PLD) * sizeof(float);
    cudaFuncSetAttribute(scan_kernel, cudaFuncAttributeMaxDynamicSharedMemorySize, scan_smem);
    const int gemm_smem = NSTAGE * 2 * GBM * SLD * sizeof(float);   // 110592
    cudaFuncSetAttribute(gemm_tf32_kernel, cudaFuncAttributeMaxDynamicSharedMemorySize, gemm_smem);

    // 1) transpose x -> (B,T,I), tf32-rounded
    transpose_kernel<<<dim3(SEQT / 32, IDIM / 32, BATCH), dim3(32, 8)>>>(x);

    // 2) xp0 = xt @ W_ih0^T
    prep_w_kernel<<<256, 256>>>(W_ih0, G4 * IDIM);
    gemm_tf32_kernel<<<dim3(G4 / GBN, (BATCH * SEQT) / GBM), 256, gemm_smem>>>(p_xt, p_w, p_xp, IDIM);

    // 3) layer-0 scan (ys0 stored tf32-rounded for GEMM2)
    zero_kernel<<<256, 256>>>();
    scan_kernel<<<SCAN_NB, SCAN_THREADS, scan_smem>>>(W_hh0, b_ih0, b_hh0, p_ys0, hid0, cell0, 1);

    // 4) xp1 = ys0 @ W_ih1^T
    prep_w_kernel<<<256, 256>>>(W_ih1, G4 * HDIM);
    gemm_tf32_kernel<<<dim3(G4 / GBN, (BATCH * SEQT) / GBM), 256, gemm_smem>>>(p_ys0, p_w, p_xp, HDIM);

    // 5) layer-1 scan (writes directly into d_out)
    zero_kernel<<<256, 256>>>();
    scan_kernel<<<SCAN_NB, SCAN_THREADS, scan_smem>>>(W_hh1, b_ih1, b_hh1, out, hid1, cell1, 0);
}